// round 13
// baseline (speedup 1.0000x reference)
#include <cuda_runtime.h>
#include <stdint.h>

// out[e,f] = (node_src[src[e],f] + off_src[e,f]) * (node_tgt[tgt[e],f] + off_tgt[e,f])
// F = 256 floats, E = 300000, N = 50000, edge_ids int32. HBM-bound.
//
// R13: streams read with ld.global.lu ("last use": cache normally, then
// deallocate the line after the read). If honored, the 614 MB of read-once
// offset traffic stops occupying L2 ways, leaving capacity for the node
// tables -> gather hit rate up. Output stores stay .cs evict-first.
// Node gathers: plain __ldg (evict_last measured as a no-op; dropped).
// 8 floats/thread; one warp = one contiguous 1 KB edge row.

#define FEAT8 32  // 256 / 8

__device__ __forceinline__ float4 ldlu4(const float4* p) {
    float4 v;
    asm volatile("ld.global.lu.v4.f32 {%0,%1,%2,%3}, [%4];"
                 : "=f"(v.x), "=f"(v.y), "=f"(v.z), "=f"(v.w)
                 : "l"(p));
    return v;
}

__global__ __launch_bounds__(256) void node_to_edge_kernel(
    const float4* __restrict__ node_src,   // [N, 64] as float4
    const float4* __restrict__ node_tgt,   // [N, 64]
    const int* __restrict__ edge_src_ids,  // [E]
    const int* __restrict__ edge_tgt_ids,  // [E]
    const float4* __restrict__ off_src,    // [E, 64]
    const float4* __restrict__ off_tgt,    // [E, 64]
    float4* __restrict__ out,              // [E, 64]
    unsigned total8)                       // E * 32
{
    unsigned idx = blockIdx.x * blockDim.x + threadIdx.x;
    if (idx >= total8) return;

    unsigned e  = idx >> 5;        // edge id
    unsigned f8 = idx & 31;        // 8-float group within row

    // Single-use stream reads first (DRAM-latency critical path):
    // last-use semantics -> line freed after the read.
    unsigned q = idx * 2;          // float4 index
    float4 b0 = ldlu4(&off_src[q]);
    float4 b1 = ldlu4(&off_src[q + 1]);
    float4 d0 = ldlu4(&off_tgt[q]);
    float4 d1 = ldlu4(&off_tgt[q + 1]);

    unsigned s = (unsigned)__ldg(&edge_src_ids[e]);
    unsigned t = (unsigned)__ldg(&edge_tgt_ids[e]);

    // Gathered node rows: default read-only path (keeps L2 residency).
    size_t sq = (size_t)s * 64 + f8 * 2;
    size_t tq = (size_t)t * 64 + f8 * 2;
    float4 a0 = __ldg(&node_src[sq]);
    float4 a1 = __ldg(&node_src[sq + 1]);
    float4 c0 = __ldg(&node_tgt[tq]);
    float4 c1 = __ldg(&node_tgt[tq + 1]);

    float4 r0, r1;
    r0.x = (a0.x + b0.x) * (c0.x + d0.x);
    r0.y = (a0.y + b0.y) * (c0.y + d0.y);
    r0.z = (a0.z + b0.z) * (c0.z + d0.z);
    r0.w = (a0.w + b0.w) * (c0.w + d0.w);
    r1.x = (a1.x + b1.x) * (c1.x + d1.x);
    r1.y = (a1.y + b1.y) * (c1.y + d1.y);
    r1.z = (a1.z + b1.z) * (c1.z + d1.z);
    r1.w = (a1.w + b1.w) * (c1.w + d1.w);

    // Output: evict-first stores.
    __stcs(&out[q], r0);
    __stcs(&out[q + 1], r1);
}

extern "C" void kernel_launch(void* const* d_in, const int* in_sizes, int n_in,
                              void* d_out, int out_size) {
    // 0: node_src_feats [N,256] f32   1: node_tgt_feats [N,256] f32
    // 2: edge_ids [2,E] int32         3: off_edge_src [E,256] f32
    // 4: off_edge_tgt [E,256] f32
    const float4* node_src = (const float4*)d_in[0];
    const float4* node_tgt = (const float4*)d_in[1];
    const int*    edge_ids = (const int*)d_in[2];
    const float4* off_src  = (const float4*)d_in[3];
    const float4* off_tgt  = (const float4*)d_in[4];
    float4*       out      = (float4*)d_out;

    unsigned E = (unsigned)(in_sizes[2] / 2);        // edge_ids has 2*E elems
    unsigned total8 = E * FEAT8;                     // 8-float groups of output

    const int* src_ids = edge_ids;                   // row 0
    const int* tgt_ids = edge_ids + E;               // row 1

    unsigned threads = 256;
    unsigned blocks = (total8 + threads - 1) / threads;
    node_to_edge_kernel<<<blocks, threads>>>(
        node_src, node_tgt, src_ids, tgt_ids, off_src, off_tgt, out, total8);
}

// round 14
// speedup vs baseline: 1.0280x; 1.0280x over previous
#include <cuda_runtime.h>
#include <stdint.h>

// out[e,f] = (node_src[src[e],f] + off_src[e,f]) * (node_tgt[tgt[e],f] + off_tgt[e,f])
// F = 256 floats, E = 300000, N = 50000, edge_ids int32. HBM-bound.
//
// R14: src-range phasing. Evidence (R8 vs R9): effective L2 capacity for
// gather reuse under the stream flood is ~35 MB. Two sequential phases by
// src-id range (blockIdx.y): phase 0 handles edges with src < N/2, phase 1
// the rest. Per-phase src working set = 25.6 MB -> L2-resident -> src gather
// DRAM ~compulsory. Streams stay in monotonic order (full 1 KB rows, 50%
// density per phase) so DRAM burst locality is preserved. No sort needed:
// warp-uniform early-exit on the src id. Streams/out use .cs evict-first.
// One warp = one edge row; 8 floats/thread; 32 B nc gather loads.

#define FEAT8 32  // 256 / 8
#define SPLIT 25000u  // N/2

struct F8 { float4 lo, hi; };

__device__ __forceinline__ F8 ldg_nc_32B(const void* p) {
    unsigned long long r0, r1, r2, r3;
    asm volatile("ld.global.nc.v4.b64 {%0,%1,%2,%3}, [%4];"
                 : "=l"(r0), "=l"(r1), "=l"(r2), "=l"(r3)
                 : "l"(p));
    F8 v;
    v.lo.x = __uint_as_float((unsigned)(r0));
    v.lo.y = __uint_as_float((unsigned)(r0 >> 32));
    v.lo.z = __uint_as_float((unsigned)(r1));
    v.lo.w = __uint_as_float((unsigned)(r1 >> 32));
    v.hi.x = __uint_as_float((unsigned)(r2));
    v.hi.y = __uint_as_float((unsigned)(r2 >> 32));
    v.hi.z = __uint_as_float((unsigned)(r3));
    v.hi.w = __uint_as_float((unsigned)(r3 >> 32));
    return v;
}

__global__ __launch_bounds__(256) void node_to_edge_kernel(
    const float* __restrict__ node_src,    // [N, 256]
    const float* __restrict__ node_tgt,    // [N, 256]
    const int* __restrict__ edge_src_ids,  // [E]
    const int* __restrict__ edge_tgt_ids,  // [E]
    const float4* __restrict__ off_src,    // [E, 64] as float4
    const float4* __restrict__ off_tgt,    // [E, 64]
    float4* __restrict__ out,              // [E, 64]
    unsigned E)
{
    unsigned tid = blockIdx.x * blockDim.x + threadIdx.x;
    unsigned e   = tid >> 5;        // edge id (warp id)
    if (e >= E) return;
    unsigned f8  = tid & 31;        // 8-float group within row

    unsigned s = (unsigned)__ldg(&edge_src_ids[e]);
    // Phase filter: phase 0 -> src < SPLIT, phase 1 -> src >= SPLIT.
    // Warp-uniform branch (s identical across the warp).
    if ((s >= SPLIT) != (blockIdx.y != 0)) return;

    unsigned t = (unsigned)__ldg(&edge_tgt_ids[e]);

    // Single-use streams: evict-first, monotonic order within the phase.
    unsigned q = (e << 6) + f8 * 2;  // float4 index in edge row
    float4 b0 = __ldcs(&off_src[q]);
    float4 b1 = __ldcs(&off_src[q + 1]);
    float4 d0 = __ldcs(&off_tgt[q]);
    float4 d1 = __ldcs(&off_tgt[q + 1]);

    // Gathered node rows: 32 B nc loads. src WS is 25.6 MB per phase.
    F8 a = ldg_nc_32B(node_src + (size_t)s * 256 + f8 * 8);
    F8 c = ldg_nc_32B(node_tgt + (size_t)t * 256 + f8 * 8);

    float4 r0, r1;
    r0.x = (a.lo.x + b0.x) * (c.lo.x + d0.x);
    r0.y = (a.lo.y + b0.y) * (c.lo.y + d0.y);
    r0.z = (a.lo.z + b0.z) * (c.lo.z + d0.z);
    r0.w = (a.lo.w + b0.w) * (c.lo.w + d0.w);
    r1.x = (a.hi.x + b1.x) * (c.hi.x + d1.x);
    r1.y = (a.hi.y + b1.y) * (c.hi.y + d1.y);
    r1.z = (a.hi.z + b1.z) * (c.hi.z + d1.z);
    r1.w = (a.hi.w + b1.w) * (c.hi.w + d1.w);

    __stcs(&out[q], r0);
    __stcs(&out[q + 1], r1);
}

extern "C" void kernel_launch(void* const* d_in, const int* in_sizes, int n_in,
                              void* d_out, int out_size) {
    // 0: node_src_feats [N,256] f32   1: node_tgt_feats [N,256] f32
    // 2: edge_ids [2,E] int32         3: off_edge_src [E,256] f32
    // 4: off_edge_tgt [E,256] f32
    const float*  node_src = (const float*)d_in[0];
    const float*  node_tgt = (const float*)d_in[1];
    const int*    edge_ids = (const int*)d_in[2];
    const float4* off_src  = (const float4*)d_in[3];
    const float4* off_tgt  = (const float4*)d_in[4];
    float4*       out      = (float4*)d_out;

    unsigned E = (unsigned)(in_sizes[2] / 2);
    const int* src_ids = edge_ids;
    const int* tgt_ids = edge_ids + E;

    // One warp per edge; 8 edges per 256-thread block; 2 phases in y.
    unsigned xblocks = (E * 32 + 255) / 256;
    dim3 grid(xblocks, 2, 1);

    node_to_edge_kernel<<<grid, 256>>>(
        node_src, node_tgt, src_ids, tgt_ids, off_src, off_tgt, out, E);
}